// round 16
// baseline (speedup 1.0000x reference)
#include <cuda_runtime.h>
#include <cuda_bf16.h>
#include <math.h>
#include <stdint.h>

#define NTOK 4096      // B*T
#define TT   2048      // T
#define DM   1024      // D = H*HD
#define DLAT 512       // DL
#define DCOMP 256      // DC
#define NH   16
#define HD   64

// ---------------- fp32 scratch ----------------
__device__ __align__(256) float g_q  [NTOK * DM];
__device__ __align__(256) float g_c  [NTOK * DCOMP];
__device__ __align__(256) float g_kv [NTOK * 2 * DM];
__device__ __align__(256) float g_rope[TT * 64];

// ---------------- bf16 split scratch (hi/lo) ----------------
__device__ __align__(256) __nv_bfloat16 g_xh [NTOK * DM],     g_xl [NTOK * DM];
__device__ __align__(256) __nv_bfloat16 g_wqh[DM * DM],       g_wql[DM * DM];
__device__ __align__(256) __nv_bfloat16 g_wkh[DLAT * DM],     g_wkl[DLAT * DM];
__device__ __align__(256) __nv_bfloat16 g_xth[NTOK * DLAT],   g_xtl[NTOK * DLAT];
__device__ __align__(256) __nv_bfloat16 g_wch[DCOMP * DLAT],  g_wcl[DCOMP * DLAT];
__device__ __align__(256) __nv_bfloat16 g_ch [NTOK * DCOMP],  g_cl [NTOK * DCOMP];
__device__ __align__(256) __nv_bfloat16 g_weh[DLAT * DCOMP],  g_wel[DLAT * DCOMP];
__device__ __align__(256) __nv_bfloat16 g_dh [NTOK * DLAT],   g_dl [NTOK * DLAT];
__device__ __align__(256) __nv_bfloat16 g_wfh[2*DM * DLAT],   g_wfl[2*DM * DLAT];
__device__ __align__(256) __nv_bfloat16 g_oh [NTOK * DM],     g_ol [NTOK * DM];
__device__ __align__(256) __nv_bfloat16 g_woh[DM * DM],       g_wol[DM * DM];
__device__ __align__(256) __nv_bfloat16 g_kvh[NTOK * 2 * DM], g_kvl[NTOK * 2 * DM];

// ================= low-level helpers (sm_80-portable ISA) =================
__device__ __forceinline__ uint32_t smem_u32(const void* p) {
    uint32_t a;
    asm("{ .reg .u64 t; cvta.to.shared.u64 t, %1; cvt.u32.u64 %0, t; }" : "=r"(a) : "l"(p));
    return a;
}
__device__ __forceinline__ void cp_async16(uint32_t saddr, const void* gaddr) {
    asm volatile("cp.async.cg.shared.global [%0], [%1], 16;" :: "r"(saddr), "l"(gaddr) : "memory");
}
__device__ __forceinline__ void cp_commit() {
    asm volatile("cp.async.commit_group;" ::: "memory");
}
template<int N>
__device__ __forceinline__ void cp_wait() {
    asm volatile("cp.async.wait_group %0;" :: "n"(N) : "memory");
}
__device__ __forceinline__ void ldmat4(uint32_t& r0, uint32_t& r1, uint32_t& r2, uint32_t& r3,
                                       uint32_t addr) {
    asm volatile("ldmatrix.sync.aligned.m8n8.x4.shared.b16 {%0,%1,%2,%3}, [%4];"
                 : "=r"(r0), "=r"(r1), "=r"(r2), "=r"(r3) : "r"(addr));
}
__device__ __forceinline__ void ldmat4t(uint32_t& r0, uint32_t& r1, uint32_t& r2, uint32_t& r3,
                                        uint32_t addr) {
    asm volatile("ldmatrix.sync.aligned.m8n8.x4.trans.shared.b16 {%0,%1,%2,%3}, [%4];"
                 : "=r"(r0), "=r"(r1), "=r"(r2), "=r"(r3) : "r"(addr));
}
__device__ __forceinline__ void mma_bf16(float* c, const uint32_t* a, const uint32_t* b) {
    asm("mma.sync.aligned.m16n8k16.row.col.f32.bf16.bf16.f32 "
        "{%0,%1,%2,%3}, {%4,%5,%6,%7}, {%8,%9}, {%0,%1,%2,%3};"
        : "+f"(c[0]), "+f"(c[1]), "+f"(c[2]), "+f"(c[3])
        : "r"(a[0]), "r"(a[1]), "r"(a[2]), "r"(a[3]), "r"(b[0]), "r"(b[1]));
}
__device__ __forceinline__ uint32_t pack2(__nv_bfloat16 a, __nv_bfloat16 b) {
    __nv_bfloat162 t; t.x = a; t.y = b;
    return *(uint32_t*)&t;
}
__device__ __forceinline__ void split1(float f, __nv_bfloat16& h, __nv_bfloat16& l) {
    h = __float2bfloat16(f);
    l = __float2bfloat16(f - __bfloat162float(h));
}

// ================= fp32 -> (hi, lo) bf16 split (optional scale) ===========
__global__ void __launch_bounds__(256)
split_bf16(const float* __restrict__ x, __nv_bfloat16* __restrict__ hi,
           __nv_bfloat16* __restrict__ lo, int n, float scale)
{
    int i = (blockIdx.x * 256 + threadIdx.x) * 4;
    if (i >= n) return;
    float4 v = *(const float4*)(x + i);
    float f[4] = {v.x * scale, v.y * scale, v.z * scale, v.w * scale};
    union { __nv_bfloat16 b[4]; uint2 u; } H, L;
    #pragma unroll
    for (int j = 0; j < 4; j++) split1(f[j], H.b[j], L.b[j]);
    *(uint2*)(hi + i) = H.u;
    *(uint2*)(lo + i) = L.u;
}

// ================= split-bf16 NT GEMM body (R12 single-barrier loop) ======
#define LDS      40
#define ARR_H    (128 * LDS)
#define STAGE_H  (4 * ARR_H)
#define STAGE_B  (STAGE_H * 2)
#define GEMM_SMEM (2 * STAGE_B)

__device__ __forceinline__ void issue_stage(
    const __nv_bfloat16* __restrict__ Ahi, const __nv_bfloat16* __restrict__ Alo,
    const __nv_bfloat16* __restrict__ Bhi, const __nv_bfloat16* __restrict__ Blo,
    int m0, int n0, int K, int k0, uint32_t sstage, int tid)
{
    const int r  = tid >> 1;
    const int cc = (tid & 1) * 16;
    const size_t goffA = (size_t)(m0 + r) * K + k0 + cc;
    const size_t goffB = (size_t)(n0 + r) * K + k0 + cc;
    const uint32_t soff = (uint32_t)(r * LDS + cc) * 2;
    cp_async16(sstage + 0*ARR_H*2 + soff,      Ahi + goffA);
    cp_async16(sstage + 0*ARR_H*2 + soff + 16, Ahi + goffA + 8);
    cp_async16(sstage + 1*ARR_H*2 + soff,      Alo + goffA);
    cp_async16(sstage + 1*ARR_H*2 + soff + 16, Alo + goffA + 8);
    cp_async16(sstage + 2*ARR_H*2 + soff,      Bhi + goffB);
    cp_async16(sstage + 2*ARR_H*2 + soff + 16, Bhi + goffB + 8);
    cp_async16(sstage + 3*ARR_H*2 + soff,      Blo + goffB);
    cp_async16(sstage + 3*ARR_H*2 + soff + 16, Blo + goffB + 8);
}

// Shared mainloop: accumulates the 128x128 tile into acc.
__device__ __forceinline__ void gemm_mainloop(
    const __nv_bfloat16* __restrict__ Ahi, const __nv_bfloat16* __restrict__ Alo,
    const __nv_bfloat16* __restrict__ Bhi, const __nv_bfloat16* __restrict__ Blo,
    int K, int m0, int n0, uint32_t sb, float acc[4][4][4])
{
    const int tid  = threadIdx.x;
    const int lane = tid & 31;
    const int w    = tid >> 5;
    const int wr   = w >> 2;
    const int wc   = w & 3;

    const uint32_t a_row = wr * 64 + (lane & 15);
    const uint32_t a_col = (lane >> 4) * 8;
    const uint32_t b_row = wc * 32 + (lane & 7) + (lane >> 4) * 8;
    const uint32_t b_col = ((lane >> 3) & 1) * 8;

    const int nk = K / 32;
    issue_stage(Ahi, Alo, Bhi, Blo, m0, n0, K, 0, sb, tid);
    cp_commit();

    for (int i = 0; i < nk; i++) {
        cp_wait<0>();
        __syncthreads();
        if (i + 1 < nk) {
            issue_stage(Ahi, Alo, Bhi, Blo, m0, n0, K, (i + 1) * 32,
                        sb + ((i + 1) & 1) * STAGE_B, tid);
            cp_commit();
        }

        const uint32_t st = sb + (i & 1) * STAGE_B;
        #pragma unroll
        for (int ks = 0; ks < 2; ks++) {
            uint32_t aH[4][4], aL[4][4], bH[4][2], bL[4][2];
            #pragma unroll
            for (int mt = 0; mt < 4; mt++) {
                const uint32_t off = ((a_row + mt*16) * LDS + ks*16 + a_col) * 2;
                ldmat4(aH[mt][0], aH[mt][1], aH[mt][2], aH[mt][3], st + 0*ARR_H*2 + off);
                ldmat4(aL[mt][0], aL[mt][1], aL[mt][2], aL[mt][3], st + 1*ARR_H*2 + off);
            }
            #pragma unroll
            for (int g = 0; g < 2; g++) {
                const uint32_t off = ((b_row + g*16) * LDS + ks*16 + b_col) * 2;
                uint32_t r0,r1,r2,r3;
                ldmat4(r0, r1, r2, r3, st + 2*ARR_H*2 + off);
                bH[2*g][0]=r0; bH[2*g][1]=r1; bH[2*g+1][0]=r2; bH[2*g+1][1]=r3;
                ldmat4(r0, r1, r2, r3, st + 3*ARR_H*2 + off);
                bL[2*g][0]=r0; bL[2*g][1]=r1; bL[2*g+1][0]=r2; bL[2*g+1][1]=r3;
            }
            #pragma unroll
            for (int mt = 0; mt < 4; mt++)
                #pragma unroll
                for (int nt = 0; nt < 4; nt++)
                    mma_bf16(acc[mt][nt], aH[mt], bH[nt]);
            #pragma unroll
            for (int mt = 0; mt < 4; mt++)
                #pragma unroll
                for (int nt = 0; nt < 4; nt++)
                    mma_bf16(acc[mt][nt], aH[mt], bL[nt]);
            #pragma unroll
            for (int mt = 0; mt < 4; mt++)
                #pragma unroll
                for (int nt = 0; nt < 4; nt++)
                    mma_bf16(acc[mt][nt], aL[mt], bH[nt]);
        }
    }
}

// OUTF = 0: write fp32 C (+bias).  OUTF = 1: write split bf16 (+bias).
template<int OUTF>
__device__ __forceinline__ void gemm_body(
    const __nv_bfloat16* __restrict__ Ahi, const __nv_bfloat16* __restrict__ Alo,
    const __nv_bfloat16* __restrict__ Bhi, const __nv_bfloat16* __restrict__ Blo,
    const float* __restrict__ bias, float* __restrict__ C,
    __nv_bfloat16* __restrict__ Ch, __nv_bfloat16* __restrict__ Cl,
    int N, int K, int bx, int by, char* smem)
{
    const uint32_t sb = smem_u32(smem);
    const int lane = threadIdx.x & 31;
    const int w    = threadIdx.x >> 5;
    const int wr   = w >> 2;
    const int wc   = w & 3;
    const int m0 = by * 128, n0 = bx * 128;

    float acc[4][4][4];
    #pragma unroll
    for (int i = 0; i < 4; i++)
        #pragma unroll
        for (int j = 0; j < 4; j++)
            #pragma unroll
            for (int e = 0; e < 4; e++) acc[i][j][e] = 0.f;

    gemm_mainloop(Ahi, Alo, Bhi, Blo, K, m0, n0, sb, acc);

    #pragma unroll
    for (int nt = 0; nt < 4; nt++) {
        const int col = n0 + wc*32 + nt*8 + (lane & 3) * 2;
        float bv0 = 0.f, bv1 = 0.f;
        if (bias) { bv0 = bias[col]; bv1 = bias[col + 1]; }
        #pragma unroll
        for (int mt = 0; mt < 4; mt++) {
            const int row = m0 + wr*64 + mt*16 + (lane >> 2);
            float v00 = acc[mt][nt][0] + bv0, v01 = acc[mt][nt][1] + bv1;
            float v10 = acc[mt][nt][2] + bv0, v11 = acc[mt][nt][3] + bv1;
            if (OUTF == 0) {
                *(float2*)(C + (size_t)row * N + col)       = make_float2(v00, v01);
                *(float2*)(C + (size_t)(row + 8) * N + col) = make_float2(v10, v11);
            } else {
                __nv_bfloat16 h0,l0,h1,l1;
                split1(v00, h0, l0); split1(v01, h1, l1);
                *(uint32_t*)(Ch + (size_t)row * N + col) = pack2(h0, h1);
                *(uint32_t*)(Cl + (size_t)row * N + col) = pack2(l0, l1);
                split1(v10, h0, l0); split1(v11, h1, l1);
                *(uint32_t*)(Ch + (size_t)(row + 8) * N + col) = pack2(h0, h1);
                *(uint32_t*)(Cl + (size_t)(row + 8) * N + col) = pack2(l0, l1);
            }
        }
    }
}

// Splice variant: out = (acc + bias) * softplus(tsc) + tsh, bf16 hi/lo out.
__device__ __forceinline__ void gemm_body_splice(
    const __nv_bfloat16* __restrict__ Ahi, const __nv_bfloat16* __restrict__ Alo,
    const __nv_bfloat16* __restrict__ Bhi, const __nv_bfloat16* __restrict__ Blo,
    const float* __restrict__ bias,
    __nv_bfloat16* __restrict__ Ch, __nv_bfloat16* __restrict__ Cl,
    int N, int K, int bx, int by, char* smem,
    const float* __restrict__ tsc, const float* __restrict__ tsh)
{
    const uint32_t sb = smem_u32(smem);
    const int lane = threadIdx.x & 31;
    const int w    = threadIdx.x >> 5;
    const int wr   = w >> 2;
    const int wc   = w & 3;
    const int m0 = by * 128, n0 = bx * 128;

    float acc[4][4][4];
    #pragma unroll
    for (int i = 0; i < 4; i++)
        #pragma unroll
        for (int j = 0; j < 4; j++)
            #pragma unroll
            for (int e = 0; e < 4; e++) acc[i][j][e] = 0.f;

    gemm_mainloop(Ahi, Alo, Bhi, Blo, K, m0, n0, sb, acc);

    #pragma unroll
    for (int nt = 0; nt < 4; nt++) {
        const int col = n0 + wc*32 + nt*8 + (lane & 3) * 2;
        const float bv0 = bias[col], bv1 = bias[col + 1];
        float xs = tsc[col];
        const float sc0 = fmaxf(xs, 0.f) + log1pf(expf(-fabsf(xs)));
        xs = tsc[col + 1];
        const float sc1 = fmaxf(xs, 0.f) + log1pf(expf(-fabsf(xs)));
        const float sh0 = tsh[col], sh1 = tsh[col + 1];
        #pragma unroll
        for (int mt = 0; mt < 4; mt++) {
            const int row = m0 + wr*64 + mt*16 + (lane >> 2);
            const float v00 = (acc[mt][nt][0] + bv0) * sc0 + sh0;
            const float v01 = (acc[mt][nt][1] + bv1) * sc1 + sh1;
            const float v10 = (acc[mt][nt][2] + bv0) * sc0 + sh0;
            const float v11 = (acc[mt][nt][3] + bv1) * sc1 + sh1;
            __nv_bfloat16 h0,l0,h1,l1;
            split1(v00, h0, l0); split1(v01, h1, l1);
            *(uint32_t*)(Ch + (size_t)row * N + col) = pack2(h0, h1);
            *(uint32_t*)(Cl + (size_t)row * N + col) = pack2(l0, l1);
            split1(v10, h0, l0); split1(v11, h1, l1);
            *(uint32_t*)(Ch + (size_t)(row + 8) * N + col) = pack2(h0, h1);
            *(uint32_t*)(Cl + (size_t)(row + 8) * N + col) = pack2(l0, l1);
        }
    }
}

// --------- standalone GEMM kernels -----------------------------------------
template<int OUTF>
__global__ void __launch_bounds__(256)
mma_gemm(const __nv_bfloat16* __restrict__ Ahi, const __nv_bfloat16* __restrict__ Alo,
         const __nv_bfloat16* __restrict__ Bhi, const __nv_bfloat16* __restrict__ Blo,
         const float* __restrict__ bias, float* __restrict__ C,
         __nv_bfloat16* __restrict__ Ch, __nv_bfloat16* __restrict__ Cl,
         int N, int K)
{
    extern __shared__ char smem[];
    gemm_body<OUTF>(Ahi, Alo, Bhi, Blo, bias, C, Ch, Cl,
                    N, K, blockIdx.x, blockIdx.y, smem);
}

// --------- merged q + xt projection (both consume x) -----------------------
// grid.x = 12: bx 0..7 -> q (N=1024, fp32 out); bx 8..11 -> xt (N=512, splice).
__global__ void __launch_bounds__(256)
mma_gemm_qxt(const __nv_bfloat16* __restrict__ xhp, const __nv_bfloat16* __restrict__ xlp,
             const __nv_bfloat16* __restrict__ wqh, const __nv_bfloat16* __restrict__ wql,
             const float* __restrict__ b_q, float* __restrict__ q,
             const __nv_bfloat16* __restrict__ wkh, const __nv_bfloat16* __restrict__ wkl,
             const float* __restrict__ b_kvl,
             __nv_bfloat16* __restrict__ xth, __nv_bfloat16* __restrict__ xtl,
             const float* __restrict__ tsc, const float* __restrict__ tsh)
{
    extern __shared__ char smem[];
    if (blockIdx.x < 8) {
        gemm_body<0>(xhp, xlp, wqh, wql, b_q, q, nullptr, nullptr,
                     DM, DM, blockIdx.x, blockIdx.y, smem);
    } else {
        gemm_body_splice(xhp, xlp, wkh, wkl, b_kvl, xth, xtl,
                         DLAT, DM, blockIdx.x - 8, blockIdx.y, smem, tsc, tsh);
    }
}

// ------------- LayerNorm over DC=256, warp/row, split-bf16 out ------------
__global__ void __launch_bounds__(256)
ln_split(const float* __restrict__ c, const float* __restrict__ g, const float* __restrict__ b,
         __nv_bfloat16* __restrict__ ch, __nv_bfloat16* __restrict__ cl)
{
    const int row  = blockIdx.x * 8 + (threadIdx.x >> 5);
    const int lane = threadIdx.x & 31;
    const float* p = c + (size_t)row * DCOMP;
    float v[8], s = 0.f, s2 = 0.f;
    #pragma unroll
    for (int u = 0; u < 8; u++) { v[u] = p[lane + 32*u]; s += v[u]; s2 += v[u]*v[u]; }
    #pragma unroll
    for (int o = 16; o; o >>= 1) {
        s  += __shfl_xor_sync(0xffffffffu, s,  o);
        s2 += __shfl_xor_sync(0xffffffffu, s2, o);
    }
    const float mu  = s * (1.f / DCOMP);
    const float var = s2 * (1.f / DCOMP) - mu * mu;
    const float r   = 1.f / sqrtf(var + 1e-5f);
    #pragma unroll
    for (int u = 0; u < 8; u++) {
        const int i = lane + 32*u;
        const float y = (v[u] - mu) * r * g[i] + b[i];
        __nv_bfloat16 h, l;
        split1(y, h, l);
        ch[(size_t)row * DCOMP + i] = h;
        cl[(size_t)row * DCOMP + i] = l;
    }
}

// ---------------- RoPE table (double trig; fast-math safe) ------
__global__ void rope_table(float* __restrict__ tab)
{
    const int t = blockIdx.x;
    const int i = threadIdx.x;
    const double inv = pow(10000.0, -(double)i / 32.0);
    const double ang = (double)t * inv;
    tab[t*64 + i]      = (float)cos(ang);
    tab[t*64 + 32 + i] = (float)sin(ang);
}

// -------- Fused: RoPE(q,k) + split q (x0.125), k, v to bf16 hi/lo --------
__global__ void __launch_bounds__(256)
rope_split(const float* __restrict__ q, const float* __restrict__ kv,
           const float* __restrict__ tab,
           __nv_bfloat16* __restrict__ qh, __nv_bfloat16* __restrict__ ql,
           __nv_bfloat16* __restrict__ kvh, __nv_bfloat16* __restrict__ kvl)
{
    const int idx = blockIdx.x * blockDim.x + threadIdx.x;
    const int d   = idx & 31;
    const int h   = (idx >> 5) & 15;
    const int tok = idx >> 9;
    const int t   = tok & (TT - 1);
    const float c = tab[t*64 + d];
    const float s = tab[t*64 + 32 + d];
    __nv_bfloat16 hh, ll;

    {
        const size_t o = (size_t)tok * DM + h*HD + d;
        const float x1 = q[o], x2 = q[o + 32];
        const float y1 = (x1*c - x2*s) * 0.125f;
        const float y2 = (x2*c + x1*s) * 0.125f;
        split1(y1, hh, ll); qh[o] = hh;      ql[o] = ll;
        split1(y2, hh, ll); qh[o + 32] = hh; ql[o + 32] = ll;
    }
    {
        const size_t o = (size_t)tok * (2*DM) + h*HD + d;
        const float x1 = kv[o], x2 = kv[o + 32];
        const float y1 = x1*c - x2*s;
        const float y2 = x2*c + x1*s;
        split1(y1, hh, ll); kvh[o] = hh;      kvl[o] = ll;
        split1(y2, hh, ll); kvh[o + 32] = hh; kvl[o + 32] = ll;
        const float v1 = kv[o + DM], v2 = kv[o + DM + 32];
        split1(v1, hh, ll); kvh[o + DM] = hh;      kvl[o + DM] = ll;
        split1(v2, hh, ll); kvh[o + DM + 32] = hh; kvl[o + DM + 32] = ll;
    }
}

// ==== Causal flash attention: 64-row Q tile, 4 warps, cp.async 2-stage KV ==
#define LDK   72
#define KVARR (64 * LDK)
#define KVSTG (4 * KVARR)
#define FLASH_SMEM (2 * KVSTG * 2)

__device__ __forceinline__ void issue_kv128(
    const __nv_bfloat16* __restrict__ khp, const __nv_bfloat16* __restrict__ klp,
    int n0, uint32_t st, int tid)
{
    #pragma unroll
    for (int u = 0; u < 4; u++) {
        const int q = tid + u * 128;
        const int r = q >> 3, c = q & 7;
        const size_t g = (size_t)(n0 + r) * (2*DM) + c * 8;
        const uint32_t so = (uint32_t)(r * LDK + c * 8) * 2;
        cp_async16(st + 0*KVARR*2 + so, khp + g);
        cp_async16(st + 1*KVARR*2 + so, klp + g);
        cp_async16(st + 2*KVARR*2 + so, khp + DM + g);
        cp_async16(st + 3*KVARR*2 + so, klp + DM + g);
    }
}

__global__ void __launch_bounds__(128)
flash_mma(const __nv_bfloat16* __restrict__ qh, const __nv_bfloat16* __restrict__ ql,
          const __nv_bfloat16* __restrict__ kvh, const __nv_bfloat16* __restrict__ kvl,
          __nv_bfloat16* __restrict__ oh, __nv_bfloat16* __restrict__ ol)
{
    extern __shared__ __nv_bfloat16 fsm[];
    const int m0   = blockIdx.x * 64;
    const int b    = blockIdx.y >> 4, h = blockIdx.y & 15;
    const int tid  = threadIdx.x, lane = tid & 31, warp = tid >> 5;

    const __nv_bfloat16* qhp = qh + (size_t)(b*TT + m0) * DM + h*HD;
    const __nv_bfloat16* qlp = ql + (size_t)(b*TT + m0) * DM + h*HD;
    const __nv_bfloat16* khp = kvh + (size_t)b * TT * (2*DM) + h*HD;
    const __nv_bfloat16* klp = kvl + (size_t)b * TT * (2*DM) + h*HD;

    const uint32_t sb = smem_u32(fsm);

    #pragma unroll
    for (int u = 0; u < 4; u++) {
        int qq = tid + u * 128;
        int r = qq >> 3, c = qq & 7;
        *(uint4*)&fsm[r*LDK + c*8]           = *(const uint4*)(qhp + (size_t)r * DM + c*8);
        *(uint4*)&fsm[KVARR + r*LDK + c*8]   = *(const uint4*)(qlp + (size_t)r * DM + c*8);
    }
    __syncthreads();

    uint32_t QH[4][4], QL[4][4];
    const uint32_t aoff = (warp*16 + (lane & 15)) * LDK + (lane >> 4) * 8;
    #pragma unroll
    for (int ks = 0; ks < 4; ks++) {
        ldmat4(QH[ks][0], QH[ks][1], QH[ks][2], QH[ks][3], sb + (aoff + ks*16) * 2);
        ldmat4(QL[ks][0], QL[ks][1], QL[ks][2], QL[ks][3], sb + (KVARR + aoff + ks*16) * 2);
    }
    __syncthreads();

    float mi[2] = {-1e30f, -1e30f}, li[2] = {0.f, 0.f};
    float O[8][4];
    #pragma unroll
    for (int j = 0; j < 8; j++)
        #pragma unroll
        for (int e = 0; e < 4; e++) O[j][e] = 0.f;

    const uint32_t brow = (lane & 7) + ((lane >> 4) << 3);
    const uint32_t bcol = ((lane >> 3) & 1) << 3;
    const uint32_t vkv  = ((lane >> 3) & 1) * 8 + (lane & 7);
    const uint32_t vd   = (lane >> 4) * 8;

    const int nt_cnt = (m0 >> 6) + 1;
    issue_kv128(khp, klp, 0, sb, tid);
    cp_commit();

    for (int it = 0; it < nt_cnt; it++) {
        const int n0 = it * 64;
        if (it + 1 < nt_cnt) {
            issue_kv128(khp, klp, n0 + 64, sb + ((it + 1) & 1) * KVSTG * 2, tid);
            cp_commit();
            cp_wait<1>();
        } else {
            cp_wait<0>();
        }
        __syncthreads();

        const uint32_t st  = sb + (it & 1) * KVSTG * 2;
        const uint32_t sKh = st, sKl = st + KVARR*2;
        const uint32_t sVh = st + 2*KVARR*2, sVl = st + 3*KVARR*2;

        float S[8][4];
        #pragma unroll
        for (int j = 0; j < 8; j++)
            #pragma unroll
            for (int e = 0; e < 4; e++) S[j][e] = 0.f;

        #pragma unroll
        for (int ks = 0; ks < 4; ks++) {
            uint32_t bH[8][2], bL[8][2];
            #pragma unroll
            for (int g = 0; g < 4; g++) {
                const uint32_t off = ((brow + g*16) * LDK + ks*16 + bcol) * 2;
                uint32_t r0,r1,r2,r3;
                ldmat4(r0, r1, r2, r3, sKh + off);
                bH[2*g][0]=r0; bH[2*g][1]=r1; bH[2*g+1][0]=r2; bH[2*g+1][1]=r3;
                ldmat4(r0, r1, r2, r3, sKl + off);
                bL[2*g][0]=r0; bL[2*g][1]=r1; bL[2*g+1][0]=r2; bL[2*g+1][1]=r3;
            }
            #pragma unroll
            for (int j = 0; j < 8; j++) mma_bf16(S[j], QH[ks], bH[j]);
            #pragma unroll
            for (int j = 0; j < 8; j++) mma_bf16(S[j], QH[ks], bL[j]);
            #pragma unroll
            for (int j = 0; j < 8; j++) mma_bf16(S[j], QL[ks], bH[j]);
        }

        if (n0 == m0) {
            const int r0 = warp*16 + (lane >> 2);
            const int cb = 2 * (lane & 3);
            #pragma unroll
            for (int j = 0; j < 8; j++) {
                const int c = j*8 + cb;
                if (c     > r0)     S[j][0] = -1e30f;
                if (c + 1 > r0)     S[j][1] = -1e30f;
                if (c     > r0 + 8) S[j][2] = -1e30f;
                if (c + 1 > r0 + 8) S[j][3] = -1e30f;
            }
        }

        float mx0 = -1e30f, mx1 = -1e30f;
        #pragma unroll
        for (int j = 0; j < 8; j++) {
            mx0 = fmaxf(mx0, fmaxf(S[j][0], S[j][1]));
            mx1 = fmaxf(mx1, fmaxf(S[j][2], S[j][3]));
        }
        mx0 = fmaxf(mx0, __shfl_xor_sync(0xffffffffu, mx0, 1));
        mx0 = fmaxf(mx0, __shfl_xor_sync(0xffffffffu, mx0, 2));
        mx1 = fmaxf(mx1, __shfl_xor_sync(0xffffffffu, mx1, 1));
        mx1 = fmaxf(mx1, __shfl_xor_sync(0xffffffffu, mx1, 2));
        const float mn0 = fmaxf(mi[0], mx0), mn1 = fmaxf(mi[1], mx1);
        const float cr0 = __expf(mi[0] - mn0), cr1 = __expf(mi[1] - mn1);
        float rs0 = 0.f, rs1 = 0.f;
        #pragma unroll
        for (int j = 0; j < 8; j++) {
            S[j][0] = __expf(S[j][0] - mn0); rs0 += S[j][0];
            S[j][1] = __expf(S[j][1] - mn0); rs0 += S[j][1];
            S[j][2] = __expf(S[j][2] - mn1); rs1 += S[j][2];
            S[j][3] = __expf(S[j][3] - mn1); rs1 += S[j][3];
        }
        rs0 += __shfl_xor_sync(0xffffffffu, rs0, 1);
        rs0 += __shfl_xor_sync(0xffffffffu, rs0, 2);
        rs1 += __shfl_xor_sync(0xffffffffu, rs1, 1);
        rs1 += __shfl_xor_sync(0xffffffffu, rs1, 2);
        li[0] = li[0] * cr0 + rs0;
        li[1] = li[1] * cr1 + rs1;
        mi[0] = mn0; mi[1] = mn1;
        #pragma unroll
        for (int j = 0; j < 8; j++) {
            O[j][0] *= cr0; O[j][1] *= cr0;
            O[j][2] *= cr1; O[j][3] *= cr1;
        }

        #pragma unroll
        for (int kk = 0; kk < 4; kk++) {
            uint32_t aPh[4], aPl[4];
            #pragma unroll
            for (int half = 0; half < 2; half++) {
                const float* Sv = S[2*kk + half];
                __nv_bfloat16 h0 = __float2bfloat16(Sv[0]);
                __nv_bfloat16 h1 = __float2bfloat16(Sv[1]);
                __nv_bfloat16 h2 = __float2bfloat16(Sv[2]);
                __nv_bfloat16 h3 = __float2bfloat16(Sv[3]);
                aPh[2*half+0] = pack2(h0, h1);
                aPh[2*half+1] = pack2(h2, h3);
                aPl[2*half+0] = pack2(__float2bfloat16(Sv[0] - __bfloat162float(h0)),
                                      __float2bfloat16(Sv[1] - __bfloat162float(h1)));
                aPl[2*half+1] = pack2(__float2bfloat16(Sv[2] - __bfloat162float(h2)),
                                      __float2bfloat16(Sv[3] - __bfloat162float(h3)));
            }
            uint32_t VH0[4][2], VH1[4][2], VL0[4][2], VL1[4][2];
            #pragma unroll
            for (int g = 0; g < 4; g++) {
                const uint32_t off = ((kk*16 + vkv) * LDK + g*16 + vd) * 2;
                ldmat4t(VH0[g][0], VH0[g][1], VH1[g][0], VH1[g][1], sVh + off);
                ldmat4t(VL0[g][0], VL0[g][1], VL1[g][0], VL1[g][1], sVl + off);
            }
            #pragma unroll
            for (int g = 0; g < 4; g++) {
                mma_bf16(O[2*g],   aPh, VH0[g]);
                mma_bf16(O[2*g+1], aPh, VH1[g]);
            }
            #pragma unroll
            for (int g = 0; g < 4; g++) {
                mma_bf16(O[2*g],   aPl, VH0[g]);
                mma_bf16(O[2*g+1], aPl, VH1[g]);
            }
            #pragma unroll
            for (int g = 0; g < 4; g++) {
                mma_bf16(O[2*g],   aPh, VL0[g]);
                mma_bf16(O[2*g+1], aPh, VL1[g]);
            }
        }
        __syncthreads();
    }

    const float inv0 = 1.f / li[0], inv1 = 1.f / li[1];
    const int row = m0 + warp*16 + (lane >> 2);
    const size_t base = (size_t)(b*TT + row) * DM + h*HD + 2*(lane & 3);
    #pragma unroll
    for (int j = 0; j < 8; j++) {
        __nv_bfloat16 h0,l0,h1,l1;
        split1(O[j][0]*inv0, h0, l0); split1(O[j][1]*inv0, h1, l1);
        *(uint32_t*)(oh + base + j*8) = pack2(h0, h1);
        *(uint32_t*)(ol + base + j*8) = pack2(l0, l1);
        split1(O[j][2]*inv1, h0, l0); split1(O[j][3]*inv1, h1, l1);
        *(uint32_t*)(oh + base + 8*DM + j*8) = pack2(h0, h1);
        *(uint32_t*)(ol + base + 8*DM + j*8) = pack2(l0, l1);
    }
}

// ---------------- launch ---------------------------------------------------
extern "C" void kernel_launch(void* const* d_in, const int* in_sizes, int n_in,
                              void* d_out, int out_size)
{
    const float* x      = (const float*)d_in[0];
    const float* W_q    = (const float*)d_in[1];
    const float* b_q    = (const float*)d_in[2];
    const float* W_kvl  = (const float*)d_in[3];
    const float* b_kvl  = (const float*)d_in[4];
    const float* ts_sc  = (const float*)d_in[5];
    const float* ts_sh  = (const float*)d_in[6];
    const float* W_comp = (const float*)d_in[7];
    const float* W_exp  = (const float*)d_in[8];
    const float* ln_g   = (const float*)d_in[9];
    const float* ln_b   = (const float*)d_in[10];
    const float* W_fkv  = (const float*)d_in[11];
    const float* b_fkv  = (const float*)d_in[12];
    const float* W_out  = (const float*)d_in[13];
    const float* b_out  = (const float*)d_in[14];
    float* out = (float*)d_out;

    float *q, *c, *kvb, *rt;
    cudaGetSymbolAddress((void**)&q,   g_q);
    cudaGetSymbolAddress((void**)&c,   g_c);
    cudaGetSymbolAddress((void**)&kvb, g_kv);
    cudaGetSymbolAddress((void**)&rt,  g_rope);

    __nv_bfloat16 *xh,*xl,*wqh,*wql,*wkh,*wkl,*xth,*xtl,*wch,*wcl,*ch,*cl,
                  *weh,*wel,*dh,*dl,*wfh,*wfl,*oh,*ol,*woh,*wol,*kvh,*kvl;
    cudaGetSymbolAddress((void**)&xh,  g_xh);  cudaGetSymbolAddress((void**)&xl,  g_xl);
    cudaGetSymbolAddress((void**)&wqh, g_wqh); cudaGetSymbolAddress((void**)&wql, g_wql);
    cudaGetSymbolAddress((void**)&wkh, g_wkh); cudaGetSymbolAddress((void**)&wkl, g_wkl);
    cudaGetSymbolAddress((void**)&xth, g_xth); cudaGetSymbolAddress((void**)&xtl, g_xtl);
    cudaGetSymbolAddress((void**)&wch, g_wch); cudaGetSymbolAddress((void**)&wcl, g_wcl);
    cudaGetSymbolAddress((void**)&ch,  g_ch);  cudaGetSymbolAddress((void**)&cl,  g_cl);
    cudaGetSymbolAddress((void**)&weh, g_weh); cudaGetSymbolAddress((void**)&wel, g_wel);
    cudaGetSymbolAddress((void**)&dh,  g_dh);  cudaGetSymbolAddress((void**)&dl,  g_dl);
    cudaGetSymbolAddress((void**)&wfh, g_wfh); cudaGetSymbolAddress((void**)&wfl, g_wfl);
    cudaGetSymbolAddress((void**)&oh,  g_oh);  cudaGetSymbolAddress((void**)&ol,  g_ol);
    cudaGetSymbolAddress((void**)&woh, g_woh); cudaGetSymbolAddress((void**)&wol, g_wol);
    cudaGetSymbolAddress((void**)&kvh, g_kvh); cudaGetSymbolAddress((void**)&kvl, g_kvl);

    cudaFuncSetAttribute(mma_gemm<0>,  cudaFuncAttributeMaxDynamicSharedMemorySize, GEMM_SMEM);
    cudaFuncSetAttribute(mma_gemm<1>,  cudaFuncAttributeMaxDynamicSharedMemorySize, GEMM_SMEM);
    cudaFuncSetAttribute(mma_gemm_qxt, cudaFuncAttributeMaxDynamicSharedMemorySize, GEMM_SMEM);
    cudaFuncSetAttribute(flash_mma,    cudaFuncAttributeMaxDynamicSharedMemorySize, FLASH_SMEM);

    rope_table<<<TT, 32>>>(rt);

    split_bf16<<<(NTOK*DM)/1024,    256>>>(x,      xh,  xl,  NTOK*DM,    1.f);
    split_bf16<<<(DM*DM)/1024,      256>>>(W_q,    wqh, wql, DM*DM,      1.f);
    split_bf16<<<(DLAT*DM)/1024,    256>>>(W_kvl,  wkh, wkl, DLAT*DM,    1.f);
    split_bf16<<<(DCOMP*DLAT)/1024, 256>>>(W_comp, wch, wcl, DCOMP*DLAT, 1.f);
    split_bf16<<<(DLAT*DCOMP)/1024, 256>>>(W_exp,  weh, wel, DLAT*DCOMP, 1.f);
    split_bf16<<<(2*DM*DLAT)/1024,  256>>>(W_fkv,  wfh, wfl, 2*DM*DLAT,  1.f);
    split_bf16<<<(DM*DM)/1024,      256>>>(W_out,  woh, wol, DM*DM,      1.f);

    // merged q + xt projections (both read x) — 384 CTAs, better occupancy
    mma_gemm_qxt<<<dim3(12, NTOK/128), 256, GEMM_SMEM>>>(
        xh, xl, wqh, wql, b_q, q, wkh, wkl, b_kvl, xth, xtl, ts_sc, ts_sh);
    mma_gemm<0><<<dim3(DCOMP/128, NTOK/128), 256, GEMM_SMEM>>>(
        xth, xtl, wch, wcl, nullptr, c, nullptr, nullptr, DCOMP, DLAT);
    ln_split<<<NTOK/8, 256>>>(c, ln_g, ln_b, ch, cl);
    mma_gemm<1><<<dim3(DLAT/128, NTOK/128), 256, GEMM_SMEM>>>(
        ch, cl, weh, wel, nullptr, nullptr, dh, dl, DLAT, DCOMP);
    mma_gemm<0><<<dim3(2*DM/128, NTOK/128), 256, GEMM_SMEM>>>(
        dh, dl, wfh, wfl, b_fkv, kvb, nullptr, nullptr, 2*DM, DLAT);
    rope_split<<<(NTOK*NH*32)/256, 256>>>(q, kvb, rt, xh, xl, kvh, kvl);
    flash_mma<<<dim3(TT/64, 2*NH), 128, FLASH_SMEM>>>(xh, xl, kvh, kvl, oh, ol);
    mma_gemm<0><<<dim3(DM/128, NTOK/128), 256, GEMM_SMEM>>>(
        oh, ol, woh, wol, b_out, out, nullptr, nullptr, DM, DM);
}

// round 17
// speedup vs baseline: 1.5593x; 1.5593x over previous
#include <cuda_runtime.h>
#include <cuda_bf16.h>
#include <math.h>
#include <stdint.h>

#define NTOK 4096      // B*T
#define TT   2048      // T
#define DM   1024      // D = H*HD
#define DLAT 512       // DL
#define DCOMP 256      // DC
#define NH   16
#define HD   64

// ---------------- fp32 scratch ----------------
__device__ __align__(256) float g_q  [NTOK * DM];
__device__ __align__(256) float g_c  [NTOK * DCOMP];
__device__ __align__(256) float g_kv [NTOK * 2 * DM];
__device__ __align__(256) float g_rope[TT * 64];

// ---------------- bf16 split scratch (hi/lo) ----------------
__device__ __align__(256) __nv_bfloat16 g_xh [NTOK * DM],     g_xl [NTOK * DM];
__device__ __align__(256) __nv_bfloat16 g_wqh[DM * DM],       g_wql[DM * DM];
__device__ __align__(256) __nv_bfloat16 g_wkh[DLAT * DM],     g_wkl[DLAT * DM];
__device__ __align__(256) __nv_bfloat16 g_xth[NTOK * DLAT],   g_xtl[NTOK * DLAT];
__device__ __align__(256) __nv_bfloat16 g_wch[DCOMP * DLAT],  g_wcl[DCOMP * DLAT];
__device__ __align__(256) __nv_bfloat16 g_ch [NTOK * DCOMP],  g_cl [NTOK * DCOMP];
__device__ __align__(256) __nv_bfloat16 g_weh[DLAT * DCOMP],  g_wel[DLAT * DCOMP];
__device__ __align__(256) __nv_bfloat16 g_dh [NTOK * DLAT],   g_dl [NTOK * DLAT];
__device__ __align__(256) __nv_bfloat16 g_wfh[2*DM * DLAT],   g_wfl[2*DM * DLAT];
__device__ __align__(256) __nv_bfloat16 g_oh [NTOK * DM],     g_ol [NTOK * DM];
__device__ __align__(256) __nv_bfloat16 g_woh[DM * DM],       g_wol[DM * DM];
__device__ __align__(256) __nv_bfloat16 g_kvh[NTOK * 2 * DM], g_kvl[NTOK * 2 * DM];

// ================= low-level helpers (sm_80-portable ISA) =================
__device__ __forceinline__ uint32_t smem_u32(const void* p) {
    uint32_t a;
    asm("{ .reg .u64 t; cvta.to.shared.u64 t, %1; cvt.u32.u64 %0, t; }" : "=r"(a) : "l"(p));
    return a;
}
__device__ __forceinline__ void cp_async16(uint32_t saddr, const void* gaddr) {
    asm volatile("cp.async.cg.shared.global [%0], [%1], 16;" :: "r"(saddr), "l"(gaddr) : "memory");
}
__device__ __forceinline__ void cp_commit() {
    asm volatile("cp.async.commit_group;" ::: "memory");
}
template<int N>
__device__ __forceinline__ void cp_wait() {
    asm volatile("cp.async.wait_group %0;" :: "n"(N) : "memory");
}
__device__ __forceinline__ void ldmat4(uint32_t& r0, uint32_t& r1, uint32_t& r2, uint32_t& r3,
                                       uint32_t addr) {
    asm volatile("ldmatrix.sync.aligned.m8n8.x4.shared.b16 {%0,%1,%2,%3}, [%4];"
                 : "=r"(r0), "=r"(r1), "=r"(r2), "=r"(r3) : "r"(addr));
}
__device__ __forceinline__ void ldmat4t(uint32_t& r0, uint32_t& r1, uint32_t& r2, uint32_t& r3,
                                        uint32_t addr) {
    asm volatile("ldmatrix.sync.aligned.m8n8.x4.trans.shared.b16 {%0,%1,%2,%3}, [%4];"
                 : "=r"(r0), "=r"(r1), "=r"(r2), "=r"(r3) : "r"(addr));
}
__device__ __forceinline__ void mma_bf16(float* c, const uint32_t* a, const uint32_t* b) {
    asm("mma.sync.aligned.m16n8k16.row.col.f32.bf16.bf16.f32 "
        "{%0,%1,%2,%3}, {%4,%5,%6,%7}, {%8,%9}, {%0,%1,%2,%3};"
        : "+f"(c[0]), "+f"(c[1]), "+f"(c[2]), "+f"(c[3])
        : "r"(a[0]), "r"(a[1]), "r"(a[2]), "r"(a[3]), "r"(b[0]), "r"(b[1]));
}
__device__ __forceinline__ uint32_t pack2(__nv_bfloat16 a, __nv_bfloat16 b) {
    __nv_bfloat162 t; t.x = a; t.y = b;
    return *(uint32_t*)&t;
}
__device__ __forceinline__ void split1(float f, __nv_bfloat16& h, __nv_bfloat16& l) {
    h = __float2bfloat16(f);
    l = __float2bfloat16(f - __bfloat162float(h));
}

// ============ merged fp32 -> (hi, lo) splits: 7 regions, one launch ========
struct SplitDesc {
    const float* src[7];
    __nv_bfloat16* hi[7];
    __nv_bfloat16* lo[7];
    int blk_end[7];    // cumulative block counts (block = 1024 elements)
};

__global__ void __launch_bounds__(256)
split_all(SplitDesc d)
{
    int r = 0;
    #pragma unroll
    for (int k = 0; k < 6; k++) r += (blockIdx.x >= (unsigned)d.blk_end[k]) ? 1 : 0;
    const int blk0 = (r == 0) ? 0 : d.blk_end[r - 1];
    const int i = ((int)blockIdx.x - blk0) * 1024 + threadIdx.x * 4;

    float4 v = *(const float4*)(d.src[r] + i);
    float f[4] = {v.x, v.y, v.z, v.w};
    union { __nv_bfloat16 b[4]; uint2 u; } H, L;
    #pragma unroll
    for (int j = 0; j < 4; j++) split1(f[j], H.b[j], L.b[j]);
    *(uint2*)(d.hi[r] + i) = H.u;
    *(uint2*)(d.lo[r] + i) = L.u;
}

// ================= split-bf16 NT GEMM (R13: single-barrier loop) ==========
#define LDS      40
#define ARR_H    (128 * LDS)
#define STAGE_H  (4 * ARR_H)
#define STAGE_B  (STAGE_H * 2)
#define GEMM_SMEM (2 * STAGE_B)

__device__ __forceinline__ void issue_stage(
    const __nv_bfloat16* __restrict__ Ahi, const __nv_bfloat16* __restrict__ Alo,
    const __nv_bfloat16* __restrict__ Bhi, const __nv_bfloat16* __restrict__ Blo,
    int m0, int n0, int K, int k0, uint32_t sstage, int tid)
{
    const int r  = tid >> 1;
    const int cc = (tid & 1) * 16;
    const size_t goffA = (size_t)(m0 + r) * K + k0 + cc;
    const size_t goffB = (size_t)(n0 + r) * K + k0 + cc;
    const uint32_t soff = (uint32_t)(r * LDS + cc) * 2;
    cp_async16(sstage + 0*ARR_H*2 + soff,      Ahi + goffA);
    cp_async16(sstage + 0*ARR_H*2 + soff + 16, Ahi + goffA + 8);
    cp_async16(sstage + 1*ARR_H*2 + soff,      Alo + goffA);
    cp_async16(sstage + 1*ARR_H*2 + soff + 16, Alo + goffA + 8);
    cp_async16(sstage + 2*ARR_H*2 + soff,      Bhi + goffB);
    cp_async16(sstage + 2*ARR_H*2 + soff + 16, Bhi + goffB + 8);
    cp_async16(sstage + 3*ARR_H*2 + soff,      Blo + goffB);
    cp_async16(sstage + 3*ARR_H*2 + soff + 16, Blo + goffB + 8);
}

// OUTF = 0: write fp32 C.  OUTF = 1: write split bf16 (Ch, Cl).
template<int SPLICE, int OUTF>
__global__ void __launch_bounds__(256)
mma_gemm(const __nv_bfloat16* __restrict__ Ahi, const __nv_bfloat16* __restrict__ Alo,
         const __nv_bfloat16* __restrict__ Bhi, const __nv_bfloat16* __restrict__ Blo,
         const float* __restrict__ bias, float* __restrict__ C,
         __nv_bfloat16* __restrict__ Ch, __nv_bfloat16* __restrict__ Cl,
         int M, int N, int K,
         const float* __restrict__ tsc, const float* __restrict__ tsh)
{
    extern __shared__ char smem[];
    const uint32_t sb = smem_u32(smem);
    const int tid  = threadIdx.x;
    const int lane = tid & 31;
    const int w    = tid >> 5;
    const int wr   = w >> 2;
    const int wc   = w & 3;
    const int m0 = blockIdx.y * 128, n0 = blockIdx.x * 128;

    float acc[4][4][4];
    #pragma unroll
    for (int i = 0; i < 4; i++)
        #pragma unroll
        for (int j = 0; j < 4; j++)
            #pragma unroll
            for (int e = 0; e < 4; e++) acc[i][j][e] = 0.f;

    const uint32_t a_row = wr * 64 + (lane & 15);
    const uint32_t a_col = (lane >> 4) * 8;
    const uint32_t b_row = wc * 32 + (lane & 7) + (lane >> 4) * 8;
    const uint32_t b_col = ((lane >> 3) & 1) * 8;

    const int nk = K / 32;
    issue_stage(Ahi, Alo, Bhi, Blo, m0, n0, K, 0, sb, tid);
    cp_commit();

    for (int i = 0; i < nk; i++) {
        cp_wait<0>();
        __syncthreads();
        if (i + 1 < nk) {
            issue_stage(Ahi, Alo, Bhi, Blo, m0, n0, K, (i + 1) * 32,
                        sb + ((i + 1) & 1) * STAGE_B, tid);
            cp_commit();
        }

        const uint32_t st = sb + (i & 1) * STAGE_B;
        #pragma unroll
        for (int ks = 0; ks < 2; ks++) {
            uint32_t aH[4][4], aL[4][4], bH[4][2], bL[4][2];
            #pragma unroll
            for (int mt = 0; mt < 4; mt++) {
                const uint32_t off = ((a_row + mt*16) * LDS + ks*16 + a_col) * 2;
                ldmat4(aH[mt][0], aH[mt][1], aH[mt][2], aH[mt][3], st + 0*ARR_H*2 + off);
                ldmat4(aL[mt][0], aL[mt][1], aL[mt][2], aL[mt][3], st + 1*ARR_H*2 + off);
            }
            #pragma unroll
            for (int g = 0; g < 2; g++) {
                const uint32_t off = ((b_row + g*16) * LDS + ks*16 + b_col) * 2;
                uint32_t r0,r1,r2,r3;
                ldmat4(r0, r1, r2, r3, st + 2*ARR_H*2 + off);
                bH[2*g][0]=r0; bH[2*g][1]=r1; bH[2*g+1][0]=r2; bH[2*g+1][1]=r3;
                ldmat4(r0, r1, r2, r3, st + 3*ARR_H*2 + off);
                bL[2*g][0]=r0; bL[2*g][1]=r1; bL[2*g+1][0]=r2; bL[2*g+1][1]=r3;
            }
            #pragma unroll
            for (int mt = 0; mt < 4; mt++)
                #pragma unroll
                for (int nt = 0; nt < 4; nt++)
                    mma_bf16(acc[mt][nt], aH[mt], bH[nt]);
            #pragma unroll
            for (int mt = 0; mt < 4; mt++)
                #pragma unroll
                for (int nt = 0; nt < 4; nt++)
                    mma_bf16(acc[mt][nt], aH[mt], bL[nt]);
            #pragma unroll
            for (int mt = 0; mt < 4; mt++)
                #pragma unroll
                for (int nt = 0; nt < 4; nt++)
                    mma_bf16(acc[mt][nt], aL[mt], bH[nt]);
        }
    }

    #pragma unroll
    for (int nt = 0; nt < 4; nt++) {
        const int col = n0 + wc*32 + nt*8 + (lane & 3) * 2;
        float bv0 = 0.f, bv1 = 0.f, sc0 = 1.f, sc1 = 1.f, sh0 = 0.f, sh1 = 0.f;
        if (bias) { bv0 = bias[col]; bv1 = bias[col + 1]; }
        if (SPLICE) {
            float xs = tsc[col];
            sc0 = fmaxf(xs, 0.f) + log1pf(expf(-fabsf(xs)));
            xs = tsc[col + 1];
            sc1 = fmaxf(xs, 0.f) + log1pf(expf(-fabsf(xs)));
            sh0 = tsh[col]; sh1 = tsh[col + 1];
        }
        #pragma unroll
        for (int mt = 0; mt < 4; mt++) {
            const int row = m0 + wr*64 + mt*16 + (lane >> 2);
            float v00 = acc[mt][nt][0] + bv0, v01 = acc[mt][nt][1] + bv1;
            float v10 = acc[mt][nt][2] + bv0, v11 = acc[mt][nt][3] + bv1;
            if (SPLICE) {
                v00 = v00 * sc0 + sh0; v01 = v01 * sc1 + sh1;
                v10 = v10 * sc0 + sh0; v11 = v11 * sc1 + sh1;
            }
            if (OUTF == 0) {
                *(float2*)(C + (size_t)row * N + col)       = make_float2(v00, v01);
                *(float2*)(C + (size_t)(row + 8) * N + col) = make_float2(v10, v11);
            } else {
                __nv_bfloat16 h0,l0,h1,l1;
                split1(v00, h0, l0); split1(v01, h1, l1);
                *(uint32_t*)(Ch + (size_t)row * N + col) = pack2(h0, h1);
                *(uint32_t*)(Cl + (size_t)row * N + col) = pack2(l0, l1);
                split1(v10, h0, l0); split1(v11, h1, l1);
                *(uint32_t*)(Ch + (size_t)(row + 8) * N + col) = pack2(h0, h1);
                *(uint32_t*)(Cl + (size_t)(row + 8) * N + col) = pack2(l0, l1);
            }
        }
    }
}

// ------------- LayerNorm over DC=256, warp/row, split-bf16 out ------------
__global__ void __launch_bounds__(256)
ln_split(const float* __restrict__ c, const float* __restrict__ g, const float* __restrict__ b,
         __nv_bfloat16* __restrict__ ch, __nv_bfloat16* __restrict__ cl)
{
    const int row  = blockIdx.x * 8 + (threadIdx.x >> 5);
    const int lane = threadIdx.x & 31;
    const float* p = c + (size_t)row * DCOMP;
    float v[8], s = 0.f, s2 = 0.f;
    #pragma unroll
    for (int u = 0; u < 8; u++) { v[u] = p[lane + 32*u]; s += v[u]; s2 += v[u]*v[u]; }
    #pragma unroll
    for (int o = 16; o; o >>= 1) {
        s  += __shfl_xor_sync(0xffffffffu, s,  o);
        s2 += __shfl_xor_sync(0xffffffffu, s2, o);
    }
    const float mu  = s * (1.f / DCOMP);
    const float var = s2 * (1.f / DCOMP) - mu * mu;
    const float r   = 1.f / sqrtf(var + 1e-5f);
    #pragma unroll
    for (int u = 0; u < 8; u++) {
        const int i = lane + 32*u;
        const float y = (v[u] - mu) * r * g[i] + b[i];
        __nv_bfloat16 h, l;
        split1(y, h, l);
        ch[(size_t)row * DCOMP + i] = h;
        cl[(size_t)row * DCOMP + i] = l;
    }
}

// ---------------- RoPE table (double trig; fast-math safe) ------
__global__ void rope_table(float* __restrict__ tab)
{
    const int t = blockIdx.x;
    const int i = threadIdx.x;
    const double inv = pow(10000.0, -(double)i / 32.0);
    const double ang = (double)t * inv;
    tab[t*64 + i]      = (float)cos(ang);
    tab[t*64 + 32 + i] = (float)sin(ang);
}

// -------- Fused: RoPE(q,k) + split q (x0.125), k, v to bf16 hi/lo --------
__global__ void __launch_bounds__(256)
rope_split(const float* __restrict__ q, const float* __restrict__ kv,
           const float* __restrict__ tab,
           __nv_bfloat16* __restrict__ qh, __nv_bfloat16* __restrict__ ql,
           __nv_bfloat16* __restrict__ kvh, __nv_bfloat16* __restrict__ kvl)
{
    const int idx = blockIdx.x * blockDim.x + threadIdx.x;
    const int d   = idx & 31;
    const int h   = (idx >> 5) & 15;
    const int tok = idx >> 9;
    const int t   = tok & (TT - 1);
    const float c = tab[t*64 + d];
    const float s = tab[t*64 + 32 + d];
    __nv_bfloat16 hh, ll;

    {
        const size_t o = (size_t)tok * DM + h*HD + d;
        const float x1 = q[o], x2 = q[o + 32];
        const float y1 = (x1*c - x2*s) * 0.125f;
        const float y2 = (x2*c + x1*s) * 0.125f;
        split1(y1, hh, ll); qh[o] = hh;      ql[o] = ll;
        split1(y2, hh, ll); qh[o + 32] = hh; ql[o + 32] = ll;
    }
    {
        const size_t o = (size_t)tok * (2*DM) + h*HD + d;
        const float x1 = kv[o], x2 = kv[o + 32];
        const float y1 = x1*c - x2*s;
        const float y2 = x2*c + x1*s;
        split1(y1, hh, ll); kvh[o] = hh;      kvl[o] = ll;
        split1(y2, hh, ll); kvh[o + 32] = hh; kvl[o + 32] = ll;
        const float v1 = kv[o + DM], v2 = kv[o + DM + 32];
        split1(v1, hh, ll); kvh[o + DM] = hh;      kvl[o + DM] = ll;
        split1(v2, hh, ll); kvh[o + DM + 32] = hh; kvl[o + DM + 32] = ll;
    }
}

// ==== Causal flash attention: 64-row Q tile, 4 warps, cp.async 2-stage KV ==
#define LDK   72
#define KVARR (64 * LDK)
#define KVSTG (4 * KVARR)
#define FLASH_SMEM (2 * KVSTG * 2)

__device__ __forceinline__ void issue_kv128(
    const __nv_bfloat16* __restrict__ khp, const __nv_bfloat16* __restrict__ klp,
    int n0, uint32_t st, int tid)
{
    #pragma unroll
    for (int u = 0; u < 4; u++) {
        const int q = tid + u * 128;
        const int r = q >> 3, c = q & 7;
        const size_t g = (size_t)(n0 + r) * (2*DM) + c * 8;
        const uint32_t so = (uint32_t)(r * LDK + c * 8) * 2;
        cp_async16(st + 0*KVARR*2 + so, khp + g);
        cp_async16(st + 1*KVARR*2 + so, klp + g);
        cp_async16(st + 2*KVARR*2 + so, khp + DM + g);
        cp_async16(st + 3*KVARR*2 + so, klp + DM + g);
    }
}

__global__ void __launch_bounds__(128)
flash_mma(const __nv_bfloat16* __restrict__ qh, const __nv_bfloat16* __restrict__ ql,
          const __nv_bfloat16* __restrict__ kvh, const __nv_bfloat16* __restrict__ kvl,
          __nv_bfloat16* __restrict__ oh, __nv_bfloat16* __restrict__ ol)
{
    extern __shared__ __nv_bfloat16 fsm[];
    const int m0   = blockIdx.x * 64;
    const int b    = blockIdx.y >> 4, h = blockIdx.y & 15;
    const int tid  = threadIdx.x, lane = tid & 31, warp = tid >> 5;

    const __nv_bfloat16* qhp = qh + (size_t)(b*TT + m0) * DM + h*HD;
    const __nv_bfloat16* qlp = ql + (size_t)(b*TT + m0) * DM + h*HD;
    const __nv_bfloat16* khp = kvh + (size_t)b * TT * (2*DM) + h*HD;
    const __nv_bfloat16* klp = kvl + (size_t)b * TT * (2*DM) + h*HD;

    const uint32_t sb = smem_u32(fsm);

    #pragma unroll
    for (int u = 0; u < 4; u++) {
        int qq = tid + u * 128;
        int r = qq >> 3, c = qq & 7;
        *(uint4*)&fsm[r*LDK + c*8]           = *(const uint4*)(qhp + (size_t)r * DM + c*8);
        *(uint4*)&fsm[KVARR + r*LDK + c*8]   = *(const uint4*)(qlp + (size_t)r * DM + c*8);
    }
    __syncthreads();

    uint32_t QH[4][4], QL[4][4];
    const uint32_t aoff = (warp*16 + (lane & 15)) * LDK + (lane >> 4) * 8;
    #pragma unroll
    for (int ks = 0; ks < 4; ks++) {
        ldmat4(QH[ks][0], QH[ks][1], QH[ks][2], QH[ks][3], sb + (aoff + ks*16) * 2);
        ldmat4(QL[ks][0], QL[ks][1], QL[ks][2], QL[ks][3], sb + (KVARR + aoff + ks*16) * 2);
    }
    __syncthreads();

    float mi[2] = {-1e30f, -1e30f}, li[2] = {0.f, 0.f};
    float O[8][4];
    #pragma unroll
    for (int j = 0; j < 8; j++)
        #pragma unroll
        for (int e = 0; e < 4; e++) O[j][e] = 0.f;

    const uint32_t brow = (lane & 7) + ((lane >> 4) << 3);
    const uint32_t bcol = ((lane >> 3) & 1) << 3;
    const uint32_t vkv  = ((lane >> 3) & 1) * 8 + (lane & 7);
    const uint32_t vd   = (lane >> 4) * 8;

    const int nt_cnt = (m0 >> 6) + 1;
    issue_kv128(khp, klp, 0, sb, tid);
    cp_commit();

    for (int it = 0; it < nt_cnt; it++) {
        const int n0 = it * 64;
        if (it + 1 < nt_cnt) {
            issue_kv128(khp, klp, n0 + 64, sb + ((it + 1) & 1) * KVSTG * 2, tid);
            cp_commit();
            cp_wait<1>();
        } else {
            cp_wait<0>();
        }
        __syncthreads();

        const uint32_t st  = sb + (it & 1) * KVSTG * 2;
        const uint32_t sKh = st, sKl = st + KVARR*2;
        const uint32_t sVh = st + 2*KVARR*2, sVl = st + 3*KVARR*2;

        float S[8][4];
        #pragma unroll
        for (int j = 0; j < 8; j++)
            #pragma unroll
            for (int e = 0; e < 4; e++) S[j][e] = 0.f;

        #pragma unroll
        for (int ks = 0; ks < 4; ks++) {
            uint32_t bH[8][2], bL[8][2];
            #pragma unroll
            for (int g = 0; g < 4; g++) {
                const uint32_t off = ((brow + g*16) * LDK + ks*16 + bcol) * 2;
                uint32_t r0,r1,r2,r3;
                ldmat4(r0, r1, r2, r3, sKh + off);
                bH[2*g][0]=r0; bH[2*g][1]=r1; bH[2*g+1][0]=r2; bH[2*g+1][1]=r3;
                ldmat4(r0, r1, r2, r3, sKl + off);
                bL[2*g][0]=r0; bL[2*g][1]=r1; bL[2*g+1][0]=r2; bL[2*g+1][1]=r3;
            }
            #pragma unroll
            for (int j = 0; j < 8; j++) mma_bf16(S[j], QH[ks], bH[j]);
            #pragma unroll
            for (int j = 0; j < 8; j++) mma_bf16(S[j], QH[ks], bL[j]);
            #pragma unroll
            for (int j = 0; j < 8; j++) mma_bf16(S[j], QL[ks], bH[j]);
        }

        if (n0 == m0) {
            const int r0 = warp*16 + (lane >> 2);
            const int cb = 2 * (lane & 3);
            #pragma unroll
            for (int j = 0; j < 8; j++) {
                const int c = j*8 + cb;
                if (c     > r0)     S[j][0] = -1e30f;
                if (c + 1 > r0)     S[j][1] = -1e30f;
                if (c     > r0 + 8) S[j][2] = -1e30f;
                if (c + 1 > r0 + 8) S[j][3] = -1e30f;
            }
        }

        float mx0 = -1e30f, mx1 = -1e30f;
        #pragma unroll
        for (int j = 0; j < 8; j++) {
            mx0 = fmaxf(mx0, fmaxf(S[j][0], S[j][1]));
            mx1 = fmaxf(mx1, fmaxf(S[j][2], S[j][3]));
        }
        mx0 = fmaxf(mx0, __shfl_xor_sync(0xffffffffu, mx0, 1));
        mx0 = fmaxf(mx0, __shfl_xor_sync(0xffffffffu, mx0, 2));
        mx1 = fmaxf(mx1, __shfl_xor_sync(0xffffffffu, mx1, 1));
        mx1 = fmaxf(mx1, __shfl_xor_sync(0xffffffffu, mx1, 2));
        const float mn0 = fmaxf(mi[0], mx0), mn1 = fmaxf(mi[1], mx1);
        const float cr0 = __expf(mi[0] - mn0), cr1 = __expf(mi[1] - mn1);
        float rs0 = 0.f, rs1 = 0.f;
        #pragma unroll
        for (int j = 0; j < 8; j++) {
            S[j][0] = __expf(S[j][0] - mn0); rs0 += S[j][0];
            S[j][1] = __expf(S[j][1] - mn0); rs0 += S[j][1];
            S[j][2] = __expf(S[j][2] - mn1); rs1 += S[j][2];
            S[j][3] = __expf(S[j][3] - mn1); rs1 += S[j][3];
        }
        rs0 += __shfl_xor_sync(0xffffffffu, rs0, 1);
        rs0 += __shfl_xor_sync(0xffffffffu, rs0, 2);
        rs1 += __shfl_xor_sync(0xffffffffu, rs1, 1);
        rs1 += __shfl_xor_sync(0xffffffffu, rs1, 2);
        li[0] = li[0] * cr0 + rs0;
        li[1] = li[1] * cr1 + rs1;
        mi[0] = mn0; mi[1] = mn1;
        #pragma unroll
        for (int j = 0; j < 8; j++) {
            O[j][0] *= cr0; O[j][1] *= cr0;
            O[j][2] *= cr1; O[j][3] *= cr1;
        }

        #pragma unroll
        for (int kk = 0; kk < 4; kk++) {
            uint32_t aPh[4], aPl[4];
            #pragma unroll
            for (int half = 0; half < 2; half++) {
                const float* Sv = S[2*kk + half];
                __nv_bfloat16 h0 = __float2bfloat16(Sv[0]);
                __nv_bfloat16 h1 = __float2bfloat16(Sv[1]);
                __nv_bfloat16 h2 = __float2bfloat16(Sv[2]);
                __nv_bfloat16 h3 = __float2bfloat16(Sv[3]);
                aPh[2*half+0] = pack2(h0, h1);
                aPh[2*half+1] = pack2(h2, h3);
                aPl[2*half+0] = pack2(__float2bfloat16(Sv[0] - __bfloat162float(h0)),
                                      __float2bfloat16(Sv[1] - __bfloat162float(h1)));
                aPl[2*half+1] = pack2(__float2bfloat16(Sv[2] - __bfloat162float(h2)),
                                      __float2bfloat16(Sv[3] - __bfloat162float(h3)));
            }
            uint32_t VH0[4][2], VH1[4][2], VL0[4][2], VL1[4][2];
            #pragma unroll
            for (int g = 0; g < 4; g++) {
                const uint32_t off = ((kk*16 + vkv) * LDK + g*16 + vd) * 2;
                ldmat4t(VH0[g][0], VH0[g][1], VH1[g][0], VH1[g][1], sVh + off);
                ldmat4t(VL0[g][0], VL0[g][1], VL1[g][0], VL1[g][1], sVl + off);
            }
            #pragma unroll
            for (int g = 0; g < 4; g++) {
                mma_bf16(O[2*g],   aPh, VH0[g]);
                mma_bf16(O[2*g+1], aPh, VH1[g]);
            }
            #pragma unroll
            for (int g = 0; g < 4; g++) {
                mma_bf16(O[2*g],   aPl, VH0[g]);
                mma_bf16(O[2*g+1], aPl, VH1[g]);
            }
            #pragma unroll
            for (int g = 0; g < 4; g++) {
                mma_bf16(O[2*g],   aPh, VL0[g]);
                mma_bf16(O[2*g+1], aPh, VL1[g]);
            }
        }
        __syncthreads();
    }

    const float inv0 = 1.f / li[0], inv1 = 1.f / li[1];
    const int row = m0 + warp*16 + (lane >> 2);
    const size_t base = (size_t)(b*TT + row) * DM + h*HD + 2*(lane & 3);
    #pragma unroll
    for (int j = 0; j < 8; j++) {
        __nv_bfloat16 h0,l0,h1,l1;
        split1(O[j][0]*inv0, h0, l0); split1(O[j][1]*inv0, h1, l1);
        *(uint32_t*)(oh + base + j*8) = pack2(h0, h1);
        *(uint32_t*)(ol + base + j*8) = pack2(l0, l1);
        split1(O[j][2]*inv1, h0, l0); split1(O[j][3]*inv1, h1, l1);
        *(uint32_t*)(oh + base + 8*DM + j*8) = pack2(h0, h1);
        *(uint32_t*)(ol + base + 8*DM + j*8) = pack2(l0, l1);
    }
}

// ---------------- launch ---------------------------------------------------
extern "C" void kernel_launch(void* const* d_in, const int* in_sizes, int n_in,
                              void* d_out, int out_size)
{
    const float* x      = (const float*)d_in[0];
    const float* W_q    = (const float*)d_in[1];
    const float* b_q    = (const float*)d_in[2];
    const float* W_kvl  = (const float*)d_in[3];
    const float* b_kvl  = (const float*)d_in[4];
    const float* ts_sc  = (const float*)d_in[5];
    const float* ts_sh  = (const float*)d_in[6];
    const float* W_comp = (const float*)d_in[7];
    const float* W_exp  = (const float*)d_in[8];
    const float* ln_g   = (const float*)d_in[9];
    const float* ln_b   = (const float*)d_in[10];
    const float* W_fkv  = (const float*)d_in[11];
    const float* b_fkv  = (const float*)d_in[12];
    const float* W_out  = (const float*)d_in[13];
    const float* b_out  = (const float*)d_in[14];
    float* out = (float*)d_out;

    float *q, *c, *kvb, *rt;
    cudaGetSymbolAddress((void**)&q,   g_q);
    cudaGetSymbolAddress((void**)&c,   g_c);
    cudaGetSymbolAddress((void**)&kvb, g_kv);
    cudaGetSymbolAddress((void**)&rt,  g_rope);

    __nv_bfloat16 *xh,*xl,*wqh,*wql,*wkh,*wkl,*xth,*xtl,*wch,*wcl,*ch,*cl,
                  *weh,*wel,*dh,*dl,*wfh,*wfl,*oh,*ol,*woh,*wol,*kvh,*kvl;
    cudaGetSymbolAddress((void**)&xh,  g_xh);  cudaGetSymbolAddress((void**)&xl,  g_xl);
    cudaGetSymbolAddress((void**)&wqh, g_wqh); cudaGetSymbolAddress((void**)&wql, g_wql);
    cudaGetSymbolAddress((void**)&wkh, g_wkh); cudaGetSymbolAddress((void**)&wkl, g_wkl);
    cudaGetSymbolAddress((void**)&xth, g_xth); cudaGetSymbolAddress((void**)&xtl, g_xtl);
    cudaGetSymbolAddress((void**)&wch, g_wch); cudaGetSymbolAddress((void**)&wcl, g_wcl);
    cudaGetSymbolAddress((void**)&ch,  g_ch);  cudaGetSymbolAddress((void**)&cl,  g_cl);
    cudaGetSymbolAddress((void**)&weh, g_weh); cudaGetSymbolAddress((void**)&wel, g_wel);
    cudaGetSymbolAddress((void**)&dh,  g_dh);  cudaGetSymbolAddress((void**)&dl,  g_dl);
    cudaGetSymbolAddress((void**)&wfh, g_wfh); cudaGetSymbolAddress((void**)&wfl, g_wfl);
    cudaGetSymbolAddress((void**)&oh,  g_oh);  cudaGetSymbolAddress((void**)&ol,  g_ol);
    cudaGetSymbolAddress((void**)&woh, g_woh); cudaGetSymbolAddress((void**)&wol, g_wol);
    cudaGetSymbolAddress((void**)&kvh, g_kvh); cudaGetSymbolAddress((void**)&kvl, g_kvl);

    cudaFuncSetAttribute(mma_gemm<0,0>, cudaFuncAttributeMaxDynamicSharedMemorySize, GEMM_SMEM);
    cudaFuncSetAttribute(mma_gemm<0,1>, cudaFuncAttributeMaxDynamicSharedMemorySize, GEMM_SMEM);
    cudaFuncSetAttribute(mma_gemm<1,1>, cudaFuncAttributeMaxDynamicSharedMemorySize, GEMM_SMEM);
    cudaFuncSetAttribute(flash_mma,     cudaFuncAttributeMaxDynamicSharedMemorySize, FLASH_SMEM);

    rope_table<<<TT, 32>>>(rt);

    // one merged split launch for x + all 6 weights (block = 1024 elems)
    SplitDesc sd;
    int acc_blk = 0;
    auto add = [&](int slot, const float* s, __nv_bfloat16* hp, __nv_bfloat16* lp, int n) {
        sd.src[slot] = s; sd.hi[slot] = hp; sd.lo[slot] = lp;
        acc_blk += n / 1024; sd.blk_end[slot] = acc_blk;
    };
    add(0, x,      xh,  xl,  NTOK*DM);
    add(1, W_q,    wqh, wql, DM*DM);
    add(2, W_kvl,  wkh, wkl, DLAT*DM);
    add(3, W_comp, wch, wcl, DCOMP*DLAT);
    add(4, W_exp,  weh, wel, DLAT*DCOMP);
    add(5, W_fkv,  wfh, wfl, 2*DM*DLAT);
    add(6, W_out,  woh, wol, DM*DM);
    split_all<<<acc_blk, 256>>>(sd);

    mma_gemm<0,0><<<dim3(DM/128, NTOK/128), 256, GEMM_SMEM>>>(
        xh, xl, wqh, wql, b_q, q, nullptr, nullptr, NTOK, DM, DM, nullptr, nullptr);
    mma_gemm<1,1><<<dim3(DLAT/128, NTOK/128), 256, GEMM_SMEM>>>(
        xh, xl, wkh, wkl, b_kvl, nullptr, xth, xtl, NTOK, DLAT, DM, ts_sc, ts_sh);
    mma_gemm<0,0><<<dim3(DCOMP/128, NTOK/128), 256, GEMM_SMEM>>>(
        xth, xtl, wch, wcl, nullptr, c, nullptr, nullptr, NTOK, DCOMP, DLAT, nullptr, nullptr);
    ln_split<<<NTOK/8, 256>>>(c, ln_g, ln_b, ch, cl);
    mma_gemm<0,1><<<dim3(DLAT/128, NTOK/128), 256, GEMM_SMEM>>>(
        ch, cl, weh, wel, nullptr, nullptr, dh, dl, NTOK, DLAT, DCOMP, nullptr, nullptr);
    mma_gemm<0,0><<<dim3(2*DM/128, NTOK/128), 256, GEMM_SMEM>>>(
        dh, dl, wfh, wfl, b_fkv, kvb, nullptr, nullptr, NTOK, 2*DM, DLAT, nullptr, nullptr);
    rope_split<<<(NTOK*NH*32)/256, 256>>>(q, kvb, rt, xh, xl, kvh, kvl);
    flash_mma<<<dim3(TT/64, 2*NH), 128, FLASH_SMEM>>>(xh, xl, kvh, kvl, oh, ol);
    mma_gemm<0,0><<<dim3(DM/128, NTOK/128), 256, GEMM_SMEM>>>(
        oh, ol, woh, wol, b_out, out, nullptr, nullptr, NTOK, DM, DM, nullptr, nullptr);
}